// round 15
// baseline (speedup 1.0000x reference)
#include <cuda_runtime.h>
#include <cuda_fp16.h>
#include <math_constants.h>
#include <cstdint>

#define BB    4
#define NN    2048
#define DIMC  768
#define HEADS 12
#define HD    64
#define MTOK  (BB * NN)   /* 8192 tokens */

// Scratch (allocation-free rule: __device__ globals)
__device__ float    g_qkv[(size_t)MTOK * 3 * DIMC];          // fp32 qkv (V region used)
__device__ uint32_t g_x16[(size_t)MTOK * (DIMC / 2)];        // x packed fp16, A-layout
__device__ uint32_t g_att16[(size_t)MTOK * (DIMC / 2)];      // attn out packed fp16, A-layout
__device__ uint32_t g_wt[(size_t)(3 * DIMC) * (DIMC / 2) + (size_t)DIMC * (DIMC / 2)]; // W^T fp16x2
__device__ uint32_t g_qt[(size_t)MTOK * (DIMC / 2)];         // Q  [bh][n][32w] fp16x2, prescaled
__device__ uint32_t g_kt[(size_t)MTOK * (DIMC / 2)];         // K  [bh][n][32w] fp16x2
__device__ uint32_t g_vt[(size_t)MTOK * (DIMC / 2)];         // V^T [bh][d][1024w] fp16x2

// ---------------------------------------------------------------------------
// fp16 helpers (sm_80+ PTX only)
// ---------------------------------------------------------------------------
__device__ __forceinline__ uint32_t packh2(float a, float b) {
    __half2 h = __floats2half2_rn(a, b);   // low = a (even k), high = b (odd k)
    return *reinterpret_cast<uint32_t*>(&h);
}

__device__ __forceinline__ void mma_f16(float* d, const uint32_t* a, const uint32_t* b) {
    asm volatile(
        "mma.sync.aligned.m16n8k16.row.col.f32.f16.f16.f32 "
        "{%0,%1,%2,%3}, {%4,%5,%6,%7}, {%8,%9}, {%0,%1,%2,%3};"
        : "+f"(d[0]), "+f"(d[1]), "+f"(d[2]), "+f"(d[3])
        : "r"(a[0]), "r"(a[1]), "r"(a[2]), "r"(a[3]), "r"(b[0]), "r"(b[1]));
}

// Word permutation within an 8-word (16-k) block: word w (k pair 2w,2w+1)
// stored at p8(w) = 2*(w&3) + (w>>2); inverse w = 4*(p&1) + (p>>1).
__device__ __forceinline__ int p8(int w)   { return ((w & 3) << 1) + (w >> 2); }
__device__ __forceinline__ int p8inv(int p){ return ((p & 1) << 2) + (p >> 1); }

// ===========================================================================
// Weight transpose + fp16 pack + word-permute:  W[768][Nc] -> WT[Nc][384w]
// ===========================================================================
__global__ void transpose_w(const float* __restrict__ W, uint32_t* __restrict__ WT, int Nc)
{
    __shared__ float tile[32][33];
    const int kb = blockIdx.y * 32;
    const int nb = blockIdx.x * 32;
    const int tx = threadIdx.x, ty = threadIdx.y;
    const int tid = ty * 16 + tx;
#pragma unroll
    for (int i = 0; i < 4; i++) {
        const int idx = i * 256 + tid;
        const int k = idx >> 5, n = idx & 31;
        tile[k][n] = W[(size_t)(kb + k) * Nc + nb + n];
    }
    __syncthreads();
    const int blk = tx >> 3, wi = tx & 7;
    const int pos = blk * 8 + p8(wi);
#pragma unroll
    for (int i = 0; i < 2; i++) {
        const int n = ty + i * 16;
        WT[(size_t)(nb + n) * (DIMC / 2) + (kb >> 1) + pos] =
            packh2(tile[2 * tx][n], tile[2 * tx + 1][n]);
    }
}

// ===========================================================================
// Prepass: x fp32 [8192][768] -> packed fp16 A-layout [8192][384w] (permuted)
// ===========================================================================
__global__ void prep_x(const float* __restrict__ x, uint32_t* __restrict__ X16)
{
    const int idx4 = blockIdx.x * 256 + threadIdx.x;
    const size_t base = (size_t)idx4 * 4;
    const int row = (int)(base / (DIMC / 2));
    const int p0  = (int)(base % (DIMC / 2));
    const float* src = x + (size_t)row * DIMC;
    uint32_t o[4];
#pragma unroll
    for (int j = 0; j < 4; j++) {
        const int p = p0 + j;
        const int w = (p & ~7) + p8inv(p & 7);
        o[j] = packh2(src[2 * w], src[2 * w + 1]);
    }
    *(uint4*)&X16[base] = make_uint4(o[0], o[1], o[2], o[3]);
}

// ===========================================================================
// Prepass: V -> V^T [bh][d][1024w] fp16x2, key-pairs word-permuted
// ===========================================================================
__global__ void prep_v(const float* __restrict__ qkv, uint32_t* __restrict__ Vt)
{
    __shared__ float tile[32][33];   // [key][d]
    const int bh = blockIdx.z;
    const int b = bh / HEADS, h = bh % HEADS;
    const int keyb = blockIdx.x * 32, db = blockIdx.y * 32;
    const int tx = threadIdx.x, ty = threadIdx.y;
    const int tid = ty * 16 + tx;
#pragma unroll
    for (int i = 0; i < 4; i++) {
        const int idx = i * 256 + tid;
        const int key = idx >> 5, d = idx & 31;
        tile[key][d] = qkv[(size_t)(b * NN + keyb + key) * (3 * DIMC)
                           + 2 * DIMC + h * HD + db + d];
    }
    __syncthreads();
    const int blk = tx >> 3, wi = tx & 7;
    const int pos = blk * 8 + p8(wi);
#pragma unroll
    for (int i = 0; i < 2; i++) {
        const int d = ty + i * 16;
        Vt[((size_t)bh * HD + db + d) * (NN / 2) + (keyb >> 1) + pos] =
            packh2(tile[2 * tx][d], tile[2 * tx + 1][d]);
    }
}

// ===========================================================================
// GEMM: C[M,N] = A[M,K] @ W[K,N] + bias[N].  Both operands prepacked fp16x2.
// 128x128 tile, BK=32, 4 warps (128 threads), warp tile 64x64 (mt=4, nt=8).
// Double-buffered smem. fused!=0: Q/K cols packed to Qt/Kt; V cols fp32 to C.
// ===========================================================================
#define GSTR 24
#define GEMM_SMEM (12288 * 4)

__global__ __launch_bounds__(128, 2)
void gemm_mma(const uint32_t* __restrict__ A16, const uint32_t* __restrict__ BT,
              const float* __restrict__ bias, float* __restrict__ C,
              uint32_t* __restrict__ Qt, uint32_t* __restrict__ Kt,
              int N, int K, int fused)
{
    extern __shared__ uint32_t dsm[];
    const int tid  = threadIdx.x;
    const int lane = tid & 31, wid = tid >> 5;      // 4 warps
    const int g = lane >> 2, t = lane & 3;
    const int bm = blockIdx.y * 128, bn = blockIdx.x * 128;
    const int wm = (wid & 1) * 64, wn = (wid >> 1) * 64;

    // fill: thread tid owns full row tid (16 words) of both A and B tiles
    const uint32_t* Aq = A16 + (size_t)(bm + tid) * (K / 2);
    const uint32_t* Bq = BT  + (size_t)(bn + tid) * (K / 2);

    float acc[4][8][4];
#pragma unroll
    for (int mt = 0; mt < 4; mt++)
#pragma unroll
        for (int nt = 0; nt < 8; nt++)
#pragma unroll
            for (int r = 0; r < 4; r++) acc[mt][nt][r] = 0.0f;

    uint4 a_ld[4], b_ld[4];

#define GEMM_LDG(kt) do {                                                    \
    _Pragma("unroll")                                                        \
    for (int i = 0; i < 4; i++) {                                            \
        a_ld[i] = *(const uint4*)(Aq + (size_t)(kt) * 16 + 4 * i);           \
        b_ld[i] = *(const uint4*)(Bq + (size_t)(kt) * 16 + 4 * i);           \
    } } while (0)

#define GEMM_STS(buf) do {                                                   \
    uint32_t* as_ = dsm + (buf) * 6144;                                      \
    uint32_t* bs_ = as_ + 3072;                                              \
    _Pragma("unroll")                                                        \
    for (int i = 0; i < 4; i++) {                                            \
        *(uint4*)&as_[tid * GSTR + 4 * i] = a_ld[i];                         \
        *(uint4*)&bs_[tid * GSTR + 4 * i] = b_ld[i];                         \
    } } while (0)

    const int NT = K / 32;
    GEMM_LDG(0);
    GEMM_STS(0);

    for (int kt = 0; kt < NT; kt++) {
        __syncthreads();
        if (kt + 1 < NT) GEMM_LDG(kt + 1);

        const uint32_t* as = dsm + (kt & 1) * 6144;
        const uint32_t* bs = as + 3072;
#pragma unroll
        for (int kb = 0; kb < 2; kb++) {
            uint32_t af[4][4], bf[8][2];
#pragma unroll
            for (int mt = 0; mt < 4; mt++) {
                const int r0 = wm + mt * 16 + g;
                uint2 lo = *(const uint2*)&as[r0 * GSTR + kb * 8 + 2 * t];
                uint2 hi = *(const uint2*)&as[(r0 + 8) * GSTR + kb * 8 + 2 * t];
                af[mt][0] = lo.x; af[mt][1] = hi.x; af[mt][2] = lo.y; af[mt][3] = hi.y;
            }
#pragma unroll
            for (int nt = 0; nt < 8; nt++) {
                uint2 bb = *(const uint2*)&bs[(wn + nt * 8 + g) * GSTR + kb * 8 + 2 * t];
                bf[nt][0] = bb.x; bf[nt][1] = bb.y;
            }
#pragma unroll
            for (int mt = 0; mt < 4; mt++)
#pragma unroll
                for (int nt = 0; nt < 8; nt++)
                    mma_f16(acc[mt][nt], af[mt], bf[nt]);
        }
        if (kt + 1 < NT) GEMM_STS((kt + 1) & 1);
    }

    // epilogue
    const bool pack_qk = (fused != 0) && (bn + wn < 1536);   // uniform per warp
#pragma unroll
    for (int mt = 0; mt < 4; mt++)
#pragma unroll
        for (int rr = 0; rr < 2; rr++) {
            const int row = bm + wm + mt * 16 + g + rr * 8;
            float* Cr = C + (size_t)row * N;
            const int btok = row >> 11, ntok = row & 2047;
#pragma unroll
            for (int nt = 0; nt < 8; nt++) {
                const int col = bn + wn + nt * 8 + 2 * t;
                float2 bb = *(const float2*)(bias + col);
                const float v0 = acc[mt][nt][rr * 2 + 0] + bb.x;
                const float v1 = acc[mt][nt][rr * 2 + 1] + bb.y;
                if (pack_qk) {
                    const bool isQ = col < 768;
                    const int within = isQ ? col : (col - 768);
                    const int h = within >> 6, d = within & 63;
                    const int w = d >> 1;
                    const int pos = (w & ~7) + p8(w & 7);
                    const uint32_t word = isQ ? packh2(v0 * 0.125f, v1 * 0.125f)
                                              : packh2(v0, v1);
                    uint32_t* dst = isQ ? Qt : Kt;
                    dst[((size_t)(btok * HEADS + h) * NN + ntok) * (HD / 2) + pos] = word;
                } else {
                    float2 o; o.x = v0; o.y = v1;
                    *(float2*)(Cr + col) = o;
                }
            }
        }
#undef GEMM_LDG
#undef GEMM_STS
}

// ===========================================================================
// Flash attention, fp16 m16n8k16. 4 warps (128 threads), warp = 32 q-rows
// (mt=2) so K/V fragments are shared across two m-tiles. Q in registers;
// P packed from registers (no P smem). K/V double-buffered, one sync/tile.
// smem words: 2 bufs x (Ks 2560 | Vs 2560) = 10240 (40960 B)
// ===========================================================================
#define AST 40
#define ATT_SMEM (10240 * 4)

__global__ __launch_bounds__(128, 2)
void attn_mma(const uint32_t* __restrict__ Qt, const uint32_t* __restrict__ Kt,
              const uint32_t* __restrict__ Vt, uint32_t* __restrict__ att16)
{
    extern __shared__ uint32_t dsm[];
    const int tid = threadIdx.x, lane = tid & 31, w = tid >> 5;   // 4 warps
    const int g = lane >> 2, t = lane & 3;
    const int qt = blockIdx.x & 15;
    const int h  = (blockIdx.x >> 4) % HEADS;
    const int b  = blockIdx.x / (16 * HEADS);
    const int bh = b * HEADS + h;
    const int q0 = qt * 128;
    const int r0 = 32 * w + g;          // warp covers rows [32w, 32w+32)

    // ---- Q fragments (two m-tiles) straight into registers ----
    uint32_t qa[2][4][4];
#pragma unroll
    for (int mt = 0; mt < 2; mt++) {
        const uint32_t* Qr0 = Qt + ((size_t)bh * NN + q0 + r0 + 16 * mt) * (HD / 2);
        const uint32_t* Qr8 = Qr0 + 8 * (HD / 2);
#pragma unroll
        for (int kb = 0; kb < 4; kb++) {
            uint2 lo = *(const uint2*)&Qr0[kb * 8 + 2 * t];
            uint2 hi = *(const uint2*)&Qr8[kb * 8 + 2 * t];
            qa[mt][kb][0] = lo.x; qa[mt][kb][1] = hi.x;
            qa[mt][kb][2] = lo.y; qa[mt][kb][3] = hi.y;
        }
    }

    float o[2][8][4];
#pragma unroll
    for (int mt = 0; mt < 2; mt++)
#pragma unroll
        for (int nt = 0; nt < 8; nt++)
#pragma unroll
            for (int r = 0; r < 4; r++) o[mt][nt][r] = 0.0f;
    float m_[2][2], l_[2][2];
#pragma unroll
    for (int mt = 0; mt < 2; mt++) {
        m_[mt][0] = -CUDART_INF_F; m_[mt][1] = -CUDART_INF_F;
        l_[mt][0] = 0.0f;          l_[mt][1] = 0.0f;
    }

    const uint32_t* Kbase = Kt + (size_t)bh * NN * (HD / 2);
    const uint32_t* Vbase = Vt + (size_t)bh * HD * (NN / 2);

    const int ld_row = tid >> 3, ld_c = (tid & 7) * 4;   // 16 rows per chunk, 4 chunks

    uint4 kf[4], vf[4];
#define ATT_LDG(kt) do {                                                      \
    _Pragma("unroll")                                                         \
    for (int j = 0; j < 4; j++) {                                             \
        kf[j] = *(const uint4*)&Kbase[((size_t)(kt) * 64 + ld_row + 16 * j) * (HD / 2) + ld_c]; \
        vf[j] = *(const uint4*)&Vbase[(size_t)(ld_row + 16 * j) * (NN / 2) + (kt) * 32 + ld_c]; \
    } } while (0)

    ATT_LDG(0);

    for (int kt = 0; kt < NN / 64; kt++) {
        const int base = (kt & 1) * 5120;           // [Ks 2560 | Vs 2560]
#pragma unroll
        for (int j = 0; j < 4; j++) {
            *(uint4*)&dsm[base + (ld_row + 16 * j) * AST + ld_c]        = kf[j];
            *(uint4*)&dsm[base + 2560 + (ld_row + 16 * j) * AST + ld_c] = vf[j];
        }
        __syncthreads();
        if (kt + 1 < NN / 64) ATT_LDG(kt + 1);   // overlaps compute below

        // ---- S = Q @ K^T : K frags shared across both m-tiles ----
        float s[2][8][4];
#pragma unroll
        for (int mt = 0; mt < 2; mt++)
#pragma unroll
            for (int nt = 0; nt < 8; nt++)
#pragma unroll
                for (int r = 0; r < 4; r++) s[mt][nt][r] = 0.0f;

#pragma unroll
        for (int kb = 0; kb < 4; kb++) {
#pragma unroll
            for (int nt = 0; nt < 8; nt++) {
                uint2 bb = *(const uint2*)&dsm[base + (nt * 8 + g) * AST + kb * 8 + 2 * t];
                uint32_t bf2[2] = {bb.x, bb.y};
                mma_f16(s[0][nt], qa[0][kb], bf2);
                mma_f16(s[1][nt], qa[1][kb], bf2);
            }
        }

        // ---- online softmax per m-tile (rows g and g+8; quad-local) ----
#pragma unroll
        for (int mt = 0; mt < 2; mt++) {
            float mx0 = -CUDART_INF_F, mx1 = -CUDART_INF_F;
#pragma unroll
            for (int nt = 0; nt < 8; nt++) {
                mx0 = fmaxf(mx0, fmaxf(s[mt][nt][0], s[mt][nt][1]));
                mx1 = fmaxf(mx1, fmaxf(s[mt][nt][2], s[mt][nt][3]));
            }
            mx0 = fmaxf(mx0, __shfl_xor_sync(0xffffffffu, mx0, 1));
            mx0 = fmaxf(mx0, __shfl_xor_sync(0xffffffffu, mx0, 2));
            mx1 = fmaxf(mx1, __shfl_xor_sync(0xffffffffu, mx1, 1));
            mx1 = fmaxf(mx1, __shfl_xor_sync(0xffffffffu, mx1, 2));
            const float nm0 = fmaxf(m_[mt][0], mx0), nm1 = fmaxf(m_[mt][1], mx1);
            const float cr0 = __expf(m_[mt][0] - nm0), cr1 = __expf(m_[mt][1] - nm1);
            float rs0 = 0.0f, rs1 = 0.0f;
#pragma unroll
            for (int nt = 0; nt < 8; nt++) {
                s[mt][nt][0] = __expf(s[mt][nt][0] - nm0);
                s[mt][nt][1] = __expf(s[mt][nt][1] - nm0);
                s[mt][nt][2] = __expf(s[mt][nt][2] - nm1);
                s[mt][nt][3] = __expf(s[mt][nt][3] - nm1);
                rs0 += s[mt][nt][0] + s[mt][nt][1];
                rs1 += s[mt][nt][2] + s[mt][nt][3];
            }
            rs0 += __shfl_xor_sync(0xffffffffu, rs0, 1);
            rs0 += __shfl_xor_sync(0xffffffffu, rs0, 2);
            rs1 += __shfl_xor_sync(0xffffffffu, rs1, 1);
            rs1 += __shfl_xor_sync(0xffffffffu, rs1, 2);
            l_[mt][0] = l_[mt][0] * cr0 + rs0;  m_[mt][0] = nm0;
            l_[mt][1] = l_[mt][1] * cr1 + rs1;  m_[mt][1] = nm1;
#pragma unroll
            for (int nt = 0; nt < 8; nt++) {
                o[mt][nt][0] *= cr0; o[mt][nt][1] *= cr0;
                o[mt][nt][2] *= cr1; o[mt][nt][3] *= cr1;
            }
        }

        // ---- O += P @ V : P from registers; V frags shared across m-tiles ----
#pragma unroll
        for (int kb = 0; kb < 4; kb++) {
            uint32_t a[2][4];
#pragma unroll
            for (int mt = 0; mt < 2; mt++) {
                a[mt][0] = packh2(s[mt][2 * kb][0],     s[mt][2 * kb][1]);
                a[mt][1] = packh2(s[mt][2 * kb][2],     s[mt][2 * kb][3]);
                a[mt][2] = packh2(s[mt][2 * kb + 1][0], s[mt][2 * kb + 1][1]);
                a[mt][3] = packh2(s[mt][2 * kb + 1][2], s[mt][2 * kb + 1][3]);
            }
#pragma unroll
            for (int nt = 0; nt < 8; nt++) {
                uint2 bb = *(const uint2*)&dsm[base + 2560 + (nt * 8 + g) * AST + kb * 8 + 2 * t];
                uint32_t bf2[2] = {bb.x, bb.y};
                mma_f16(o[0][nt], a[0], bf2);
                mma_f16(o[1][nt], a[1], bf2);
            }
        }
    }

    // ---- epilogue: normalize, write packed fp16 in GEMM-A layout ----
#pragma unroll
    for (int mt = 0; mt < 2; mt++) {
        const float inv0 = 1.0f / l_[mt][0], inv1 = 1.0f / l_[mt][1];
        const int grow = b * NN + q0 + r0 + 16 * mt;
        uint32_t* ar0 = att16 + (size_t)grow * (DIMC / 2);
        uint32_t* ar1 = att16 + (size_t)(grow + 8) * (DIMC / 2);
#pragma unroll
        for (int nt = 0; nt < 8; nt++) {
            const int wd = h * 32 + 4 * nt + t;            // global word index
            const int pos = (wd & ~7) + p8(wd & 7);
            ar0[pos] = packh2(o[mt][nt][0] * inv0, o[mt][nt][1] * inv0);
            ar1[pos] = packh2(o[mt][nt][2] * inv1, o[mt][nt][3] * inv1);
        }
    }
#undef ATT_LDG
}

// ---------------------------------------------------------------------------
extern "C" void kernel_launch(void* const* d_in, const int* in_sizes, int n_in,
                              void* d_out, int out_size)
{
    const float* x      = (const float*)d_in[0];
    const float* w_qkv  = (const float*)d_in[1];
    const float* b_qkv  = (const float*)d_in[2];
    const float* w_proj = (const float*)d_in[3];
    const float* b_proj = (const float*)d_in[4];
    float* out = (float*)d_out;

    float *qkv_s = nullptr;
    uint32_t *x16_s = nullptr, *att16_s = nullptr;
    uint32_t *wt_s = nullptr, *qt_s = nullptr, *kt_s = nullptr, *vt_s = nullptr;
    cudaGetSymbolAddress((void**)&qkv_s,  g_qkv);
    cudaGetSymbolAddress((void**)&x16_s,  g_x16);
    cudaGetSymbolAddress((void**)&att16_s, g_att16);
    cudaGetSymbolAddress((void**)&wt_s,   g_wt);
    cudaGetSymbolAddress((void**)&qt_s,   g_qt);
    cudaGetSymbolAddress((void**)&kt_s,   g_kt);
    cudaGetSymbolAddress((void**)&vt_s,   g_vt);

    cudaFuncSetAttribute(gemm_mma, cudaFuncAttributeMaxDynamicSharedMemorySize, GEMM_SMEM);
    cudaFuncSetAttribute(attn_mma, cudaFuncAttributeMaxDynamicSharedMemorySize, ATT_SMEM);

    uint32_t* wqkvT = wt_s;
    uint32_t* wprjT = wt_s + (size_t)(3 * DIMC) * (DIMC / 2);

    // 0) weight transposes + x packing (fp16, word-permuted)
    transpose_w<<<dim3((3 * DIMC) / 32, DIMC / 32), dim3(16, 16)>>>(w_qkv, wqkvT, 3 * DIMC);
    transpose_w<<<dim3(DIMC / 32, DIMC / 32), dim3(16, 16)>>>(w_proj, wprjT, DIMC);
    prep_x<<<(MTOK * (DIMC / 2)) / 1024, 256>>>(x, x16_s);

    // 1) QKV GEMM with fused Q/K packing (V written fp32 to g_qkv)
    gemm_mma<<<dim3((3 * DIMC) / 128, MTOK / 128), 128, GEMM_SMEM>>>(
        x16_s, wqkvT, b_qkv, qkv_s, qt_s, kt_s, 3 * DIMC, DIMC, 1);

    // 2) prepass: V transposed fp16 packed
    prep_v<<<dim3(NN / 32, HD / 32, BB * HEADS), dim3(16, 16)>>>(qkv_s, vt_s);

    // 3) flash attention (output packed fp16 in GEMM-A layout)
    attn_mma<<<BB * HEADS * 16, 128, ATT_SMEM>>>(qt_s, kt_s, vt_s, att16_s);

    // 4) projection GEMM: [8192,768] @ [768,768] + bias (fp32 out)
    gemm_mma<<<dim3(DIMC / 128, MTOK / 128), 128, GEMM_SMEM>>>(
        att16_s, wprjT, b_proj, out, nullptr, nullptr, DIMC, DIMC, 0);
}

// round 16
// speedup vs baseline: 1.1533x; 1.1533x over previous
#include <cuda_runtime.h>
#include <cuda_fp16.h>
#include <math_constants.h>
#include <cstdint>

#define BB    4
#define NN    2048
#define DIMC  768
#define HEADS 12
#define HD    64
#define MTOK  (BB * NN)   /* 8192 tokens */

// Scratch (allocation-free rule: __device__ globals)
__device__ float    g_qkv[(size_t)MTOK * 3 * DIMC];          // fp32 qkv (V region used)
__device__ uint32_t g_x16[(size_t)MTOK * (DIMC / 2)];        // x packed fp16, A-layout
__device__ uint32_t g_att16[(size_t)MTOK * (DIMC / 2)];      // attn out packed fp16, A-layout
__device__ uint32_t g_wt[(size_t)(3 * DIMC) * (DIMC / 2) + (size_t)DIMC * (DIMC / 2)]; // W^T fp16x2
__device__ uint32_t g_qt[(size_t)MTOK * (DIMC / 2)];         // Q  [bh][n][32w] fp16x2, prescaled
__device__ uint32_t g_kt[(size_t)MTOK * (DIMC / 2)];         // K  [bh][n][32w] fp16x2
__device__ uint32_t g_vt[(size_t)MTOK * (DIMC / 2)];         // V^T [bh][d][1024w] fp16x2

// ---------------------------------------------------------------------------
// fp16 helpers (sm_80+ PTX only)
// ---------------------------------------------------------------------------
__device__ __forceinline__ uint32_t packh2(float a, float b) {
    __half2 h = __floats2half2_rn(a, b);   // low = a (even k), high = b (odd k)
    return *reinterpret_cast<uint32_t*>(&h);
}

__device__ __forceinline__ void mma_f16(float* d, const uint32_t* a, const uint32_t* b) {
    asm volatile(
        "mma.sync.aligned.m16n8k16.row.col.f32.f16.f16.f32 "
        "{%0,%1,%2,%3}, {%4,%5,%6,%7}, {%8,%9}, {%0,%1,%2,%3};"
        : "+f"(d[0]), "+f"(d[1]), "+f"(d[2]), "+f"(d[3])
        : "r"(a[0]), "r"(a[1]), "r"(a[2]), "r"(a[3]), "r"(b[0]), "r"(b[1]));
}

// Word permutation within an 8-word (16-k) block: word w (k pair 2w,2w+1)
// stored at p8(w) = 2*(w&3) + (w>>2); inverse w = 4*(p&1) + (p>>1).
__device__ __forceinline__ int p8(int w)   { return ((w & 3) << 1) + (w >> 2); }
__device__ __forceinline__ int p8inv(int p){ return ((p & 1) << 2) + (p >> 1); }

// ===========================================================================
// Weight transpose + fp16 pack + word-permute:  W[768][Nc] -> WT[Nc][384w]
// ===========================================================================
__global__ void transpose_w(const float* __restrict__ W, uint32_t* __restrict__ WT, int Nc)
{
    __shared__ float tile[32][33];
    const int kb = blockIdx.y * 32;
    const int nb = blockIdx.x * 32;
    const int tx = threadIdx.x, ty = threadIdx.y;
    const int tid = ty * 16 + tx;
#pragma unroll
    for (int i = 0; i < 4; i++) {
        const int idx = i * 256 + tid;
        const int k = idx >> 5, n = idx & 31;
        tile[k][n] = W[(size_t)(kb + k) * Nc + nb + n];
    }
    __syncthreads();
    const int blk = tx >> 3, wi = tx & 7;
    const int pos = blk * 8 + p8(wi);
#pragma unroll
    for (int i = 0; i < 2; i++) {
        const int n = ty + i * 16;
        WT[(size_t)(nb + n) * (DIMC / 2) + (kb >> 1) + pos] =
            packh2(tile[2 * tx][n], tile[2 * tx + 1][n]);
    }
}

// ===========================================================================
// Prepass: x fp32 [8192][768] -> packed fp16 A-layout [8192][384w] (permuted)
// ===========================================================================
__global__ void prep_x(const float* __restrict__ x, uint32_t* __restrict__ X16)
{
    const int idx4 = blockIdx.x * 256 + threadIdx.x;
    const size_t base = (size_t)idx4 * 4;
    const int row = (int)(base / (DIMC / 2));
    const int p0  = (int)(base % (DIMC / 2));
    const float* src = x + (size_t)row * DIMC;
    uint32_t o[4];
#pragma unroll
    for (int j = 0; j < 4; j++) {
        const int p = p0 + j;
        const int w = (p & ~7) + p8inv(p & 7);
        o[j] = packh2(src[2 * w], src[2 * w + 1]);
    }
    *(uint4*)&X16[base] = make_uint4(o[0], o[1], o[2], o[3]);
}

// ===========================================================================
// Prepass: V -> V^T [bh][d][1024w] fp16x2, key-pairs word-permuted
// ===========================================================================
__global__ void prep_v(const float* __restrict__ qkv, uint32_t* __restrict__ Vt)
{
    __shared__ float tile[32][33];   // [key][d]
    const int bh = blockIdx.z;
    const int b = bh / HEADS, h = bh % HEADS;
    const int keyb = blockIdx.x * 32, db = blockIdx.y * 32;
    const int tx = threadIdx.x, ty = threadIdx.y;
    const int tid = ty * 16 + tx;
#pragma unroll
    for (int i = 0; i < 4; i++) {
        const int idx = i * 256 + tid;
        const int key = idx >> 5, d = idx & 31;
        tile[key][d] = qkv[(size_t)(b * NN + keyb + key) * (3 * DIMC)
                           + 2 * DIMC + h * HD + db + d];
    }
    __syncthreads();
    const int blk = tx >> 3, wi = tx & 7;
    const int pos = blk * 8 + p8(wi);
#pragma unroll
    for (int i = 0; i < 2; i++) {
        const int d = ty + i * 16;
        Vt[((size_t)bh * HD + db + d) * (NN / 2) + (keyb >> 1) + pos] =
            packh2(tile[2 * tx][d], tile[2 * tx + 1][d]);
    }
}

// ===========================================================================
// GEMM (R14-proven config): C[M,N] = A[M,K] @ W[K,N] + bias[N].
// 128x128 tile, BK=32, 8 warps (256 threads), warp tile 32x64 (mt=2, nt=8).
// Double-buffered smem. fused!=0: Q/K cols packed to Qt/Kt; V cols fp32 to C.
// ===========================================================================
#define GSTR 24
#define GEMM_SMEM (12288 * 4)

__global__ __launch_bounds__(256, 2)
void gemm_mma(const uint32_t* __restrict__ A16, const uint32_t* __restrict__ BT,
              const float* __restrict__ bias, float* __restrict__ C,
              uint32_t* __restrict__ Qt, uint32_t* __restrict__ Kt,
              int N, int K, int fused)
{
    extern __shared__ uint32_t dsm[];
    const int tid  = threadIdx.x;
    const int lane = tid & 31, wid = tid >> 5;
    const int g = lane >> 2, t = lane & 3;
    const int bm = blockIdx.y * 128, bn = blockIdx.x * 128;
    const int wm = (wid & 3) * 32, wn = (wid >> 2) * 64;

    const int ar  = tid >> 1;
    const int ablk = tid & 1;
    const uint32_t* Aq = A16 + (size_t)(bm + ar) * (K / 2) + ablk * 8;
    const uint32_t* Bq = BT  + (size_t)(bn + ar) * (K / 2) + ablk * 8;

    float acc[2][8][4];
#pragma unroll
    for (int mt = 0; mt < 2; mt++)
#pragma unroll
        for (int nt = 0; nt < 8; nt++)
#pragma unroll
            for (int r = 0; r < 4; r++) acc[mt][nt][r] = 0.0f;

    uint4 a_ld[2], b_ld[2];

#define GEMM_LDG(kt) do {                                                    \
    a_ld[0] = *(const uint4*)(Aq + (size_t)(kt) * 16);                       \
    a_ld[1] = *(const uint4*)(Aq + (size_t)(kt) * 16 + 4);                   \
    b_ld[0] = *(const uint4*)(Bq + (size_t)(kt) * 16);                       \
    b_ld[1] = *(const uint4*)(Bq + (size_t)(kt) * 16 + 4);                   \
    } while (0)

#define GEMM_STS(buf) do {                                                   \
    uint32_t* as_ = dsm + (buf) * 6144;                                      \
    uint32_t* bs_ = as_ + 3072;                                              \
    *(uint4*)&as_[ar * GSTR + ablk * 8]     = a_ld[0];                       \
    *(uint4*)&as_[ar * GSTR + ablk * 8 + 4] = a_ld[1];                       \
    *(uint4*)&bs_[ar * GSTR + ablk * 8]     = b_ld[0];                       \
    *(uint4*)&bs_[ar * GSTR + ablk * 8 + 4] = b_ld[1];                       \
    } while (0)

    const int NT = K / 32;
    GEMM_LDG(0);
    GEMM_STS(0);

    for (int kt = 0; kt < NT; kt++) {
        __syncthreads();
        if (kt + 1 < NT) GEMM_LDG(kt + 1);

        const uint32_t* as = dsm + (kt & 1) * 6144;
        const uint32_t* bs = as + 3072;
#pragma unroll
        for (int kb = 0; kb < 2; kb++) {
            uint32_t af[2][4], bf[8][2];
#pragma unroll
            for (int mt = 0; mt < 2; mt++) {
                const int r0 = wm + mt * 16 + g;
                uint2 lo = *(const uint2*)&as[r0 * GSTR + kb * 8 + 2 * t];
                uint2 hi = *(const uint2*)&as[(r0 + 8) * GSTR + kb * 8 + 2 * t];
                af[mt][0] = lo.x; af[mt][1] = hi.x; af[mt][2] = lo.y; af[mt][3] = hi.y;
            }
#pragma unroll
            for (int nt = 0; nt < 8; nt++) {
                uint2 bb = *(const uint2*)&bs[(wn + nt * 8 + g) * GSTR + kb * 8 + 2 * t];
                bf[nt][0] = bb.x; bf[nt][1] = bb.y;
            }
#pragma unroll
            for (int mt = 0; mt < 2; mt++)
#pragma unroll
                for (int nt = 0; nt < 8; nt++)
                    mma_f16(acc[mt][nt], af[mt], bf[nt]);
        }
        if (kt + 1 < NT) GEMM_STS((kt + 1) & 1);
    }

    // epilogue
    const bool pack_qk = (fused != 0) && (bn + wn < 1536);   // uniform per warp
#pragma unroll
    for (int mt = 0; mt < 2; mt++)
#pragma unroll
        for (int rr = 0; rr < 2; rr++) {
            const int row = bm + wm + mt * 16 + g + rr * 8;
            float* Cr = C + (size_t)row * N;
            const int btok = row >> 11, ntok = row & 2047;
#pragma unroll
            for (int nt = 0; nt < 8; nt++) {
                const int col = bn + wn + nt * 8 + 2 * t;
                float2 bb = *(const float2*)(bias + col);
                const float v0 = acc[mt][nt][rr * 2 + 0] + bb.x;
                const float v1 = acc[mt][nt][rr * 2 + 1] + bb.y;
                if (pack_qk) {
                    const bool isQ = col < 768;
                    const int within = isQ ? col : (col - 768);
                    const int h = within >> 6, d = within & 63;
                    const int w = d >> 1;
                    const int pos = (w & ~7) + p8(w & 7);
                    const uint32_t word = isQ ? packh2(v0 * 0.125f, v1 * 0.125f)
                                              : packh2(v0, v1);
                    uint32_t* dst = isQ ? Qt : Kt;
                    dst[((size_t)(btok * HEADS + h) * NN + ntok) * (HD / 2) + pos] = word;
                } else {
                    float2 o; o.x = v0; o.y = v1;
                    *(float2*)(Cr + col) = o;
                }
            }
        }
#undef GEMM_LDG
#undef GEMM_STS
}

// ===========================================================================
// Flash attention, fp16 m16n8k16. 8 warps (256 threads), q-tile = 256 rows:
// warp = 32 q-rows (mt=2, K/V frags shared across m-tiles), fills amortized
// over 2x q-rows. Q in registers; P packed from registers (no P smem).
// K/V double-buffered, one sync per tile.
// smem words: 2 bufs x (Ks 2560 | Vs 2560) = 10240 (40960 B)
// ===========================================================================
#define AST 40
#define ATT_SMEM (10240 * 4)

__global__ __launch_bounds__(256, 1)
void attn_mma(const uint32_t* __restrict__ Qt, const uint32_t* __restrict__ Kt,
              const uint32_t* __restrict__ Vt, uint32_t* __restrict__ att16)
{
    extern __shared__ uint32_t dsm[];
    const int tid = threadIdx.x, lane = tid & 31, w = tid >> 5;   // 8 warps
    const int g = lane >> 2, t = lane & 3;
    const int qt = blockIdx.x & 7;                 // 8 q-tiles of 256
    const int h  = (blockIdx.x >> 3) % HEADS;
    const int b  = blockIdx.x / (8 * HEADS);
    const int bh = b * HEADS + h;
    const int q0 = qt * 256;
    const int r0 = 32 * w + g;          // warp covers rows [32w, 32w+32)

    // ---- Q fragments (two m-tiles) straight into registers ----
    uint32_t qa[2][4][4];
#pragma unroll
    for (int mt = 0; mt < 2; mt++) {
        const uint32_t* Qr0 = Qt + ((size_t)bh * NN + q0 + r0 + 16 * mt) * (HD / 2);
        const uint32_t* Qr8 = Qr0 + 8 * (HD / 2);
#pragma unroll
        for (int kb = 0; kb < 4; kb++) {
            uint2 lo = *(const uint2*)&Qr0[kb * 8 + 2 * t];
            uint2 hi = *(const uint2*)&Qr8[kb * 8 + 2 * t];
            qa[mt][kb][0] = lo.x; qa[mt][kb][1] = hi.x;
            qa[mt][kb][2] = lo.y; qa[mt][kb][3] = hi.y;
        }
    }

    float o[2][8][4];
#pragma unroll
    for (int mt = 0; mt < 2; mt++)
#pragma unroll
        for (int nt = 0; nt < 8; nt++)
#pragma unroll
            for (int r = 0; r < 4; r++) o[mt][nt][r] = 0.0f;
    float m_[2][2], l_[2][2];
#pragma unroll
    for (int mt = 0; mt < 2; mt++) {
        m_[mt][0] = -CUDART_INF_F; m_[mt][1] = -CUDART_INF_F;
        l_[mt][0] = 0.0f;          l_[mt][1] = 0.0f;
    }

    const uint32_t* Kbase = Kt + (size_t)bh * NN * (HD / 2);
    const uint32_t* Vbase = Vt + (size_t)bh * HD * (NN / 2);

    const int ld_row = tid >> 3, ld_c = (tid & 7) * 4;   // 32 rows/chunk, 2 chunks

    uint4 kf[2], vf[2];
#define ATT_LDG(kt) do {                                                      \
    _Pragma("unroll")                                                         \
    for (int j = 0; j < 2; j++) {                                             \
        kf[j] = *(const uint4*)&Kbase[((size_t)(kt) * 64 + ld_row + 32 * j) * (HD / 2) + ld_c]; \
        vf[j] = *(const uint4*)&Vbase[(size_t)(ld_row + 32 * j) * (NN / 2) + (kt) * 32 + ld_c]; \
    } } while (0)

    ATT_LDG(0);

    for (int kt = 0; kt < NN / 64; kt++) {
        const int base = (kt & 1) * 5120;           // [Ks 2560 | Vs 2560]
#pragma unroll
        for (int j = 0; j < 2; j++) {
            *(uint4*)&dsm[base + (ld_row + 32 * j) * AST + ld_c]        = kf[j];
            *(uint4*)&dsm[base + 2560 + (ld_row + 32 * j) * AST + ld_c] = vf[j];
        }
        __syncthreads();
        if (kt + 1 < NN / 64) ATT_LDG(kt + 1);   // overlaps compute below

        // ---- S = Q @ K^T : K frags shared across both m-tiles ----
        float s[2][8][4];
#pragma unroll
        for (int mt = 0; mt < 2; mt++)
#pragma unroll
            for (int nt = 0; nt < 8; nt++)
#pragma unroll
                for (int r = 0; r < 4; r++) s[mt][nt][r] = 0.0f;

#pragma unroll
        for (int kb = 0; kb < 4; kb++) {
#pragma unroll
            for (int nt = 0; nt < 8; nt++) {
                uint2 bb = *(const uint2*)&dsm[base + (nt * 8 + g) * AST + kb * 8 + 2 * t];
                uint32_t bf2[2] = {bb.x, bb.y};
                mma_f16(s[0][nt], qa[0][kb], bf2);
                mma_f16(s[1][nt], qa[1][kb], bf2);
            }
        }

        // ---- online softmax per m-tile (rows g and g+8; quad-local) ----
#pragma unroll
        for (int mt = 0; mt < 2; mt++) {
            float mx0 = -CUDART_INF_F, mx1 = -CUDART_INF_F;
#pragma unroll
            for (int nt = 0; nt < 8; nt++) {
                mx0 = fmaxf(mx0, fmaxf(s[mt][nt][0], s[mt][nt][1]));
                mx1 = fmaxf(mx1, fmaxf(s[mt][nt][2], s[mt][nt][3]));
            }
            mx0 = fmaxf(mx0, __shfl_xor_sync(0xffffffffu, mx0, 1));
            mx0 = fmaxf(mx0, __shfl_xor_sync(0xffffffffu, mx0, 2));
            mx1 = fmaxf(mx1, __shfl_xor_sync(0xffffffffu, mx1, 1));
            mx1 = fmaxf(mx1, __shfl_xor_sync(0xffffffffu, mx1, 2));
            const float nm0 = fmaxf(m_[mt][0], mx0), nm1 = fmaxf(m_[mt][1], mx1);
            const float cr0 = __expf(m_[mt][0] - nm0), cr1 = __expf(m_[mt][1] - nm1);
            float rs0 = 0.0f, rs1 = 0.0f;
#pragma unroll
            for (int nt = 0; nt < 8; nt++) {
                s[mt][nt][0] = __expf(s[mt][nt][0] - nm0);
                s[mt][nt][1] = __expf(s[mt][nt][1] - nm0);
                s[mt][nt][2] = __expf(s[mt][nt][2] - nm1);
                s[mt][nt][3] = __expf(s[mt][nt][3] - nm1);
                rs0 += s[mt][nt][0] + s[mt][nt][1];
                rs1 += s[mt][nt][2] + s[mt][nt][3];
            }
            rs0 += __shfl_xor_sync(0xffffffffu, rs0, 1);
            rs0 += __shfl_xor_sync(0xffffffffu, rs0, 2);
            rs1 += __shfl_xor_sync(0xffffffffu, rs1, 1);
            rs1 += __shfl_xor_sync(0xffffffffu, rs1, 2);
            l_[mt][0] = l_[mt][0] * cr0 + rs0;  m_[mt][0] = nm0;
            l_[mt][1] = l_[mt][1] * cr1 + rs1;  m_[mt][1] = nm1;
#pragma unroll
            for (int nt = 0; nt < 8; nt++) {
                o[mt][nt][0] *= cr0; o[mt][nt][1] *= cr0;
                o[mt][nt][2] *= cr1; o[mt][nt][3] *= cr1;
            }
        }

        // ---- O += P @ V : P from registers; V frags shared across m-tiles ----
#pragma unroll
        for (int kb = 0; kb < 4; kb++) {
            uint32_t a[2][4];
#pragma unroll
            for (int mt = 0; mt < 2; mt++) {
                a[mt][0] = packh2(s[mt][2 * kb][0],     s[mt][2 * kb][1]);
                a[mt][1] = packh2(s[mt][2 * kb][2],     s[mt][2 * kb][3]);
                a[mt][2] = packh2(s[mt][2 * kb + 1][0], s[mt][2 * kb + 1][1]);
                a[mt][3] = packh2(s[mt][2 * kb + 1][2], s[mt][2 * kb + 1][3]);
            }
#pragma unroll
            for (int nt = 0; nt < 8; nt++) {
                uint2 bb = *(const uint2*)&dsm[base + 2560 + (nt * 8 + g) * AST + kb * 8 + 2 * t];
                uint32_t bf2[2] = {bb.x, bb.y};
                mma_f16(o[0][nt], a[0], bf2);
                mma_f16(o[1][nt], a[1], bf2);
            }
        }
    }

    // ---- epilogue: normalize, write packed fp16 in GEMM-A layout ----
#pragma unroll
    for (int mt = 0; mt < 2; mt++) {
        const float inv0 = 1.0f / l_[mt][0], inv1 = 1.0f / l_[mt][1];
        const int grow = b * NN + q0 + r0 + 16 * mt;
        uint32_t* ar0 = att16 + (size_t)grow * (DIMC / 2);
        uint32_t* ar1 = att16 + (size_t)(grow + 8) * (DIMC / 2);
#pragma unroll
        for (int nt = 0; nt < 8; nt++) {
            const int wd = h * 32 + 4 * nt + t;            // global word index
            const int pos = (wd & ~7) + p8(wd & 7);
            ar0[pos] = packh2(o[mt][nt][0] * inv0, o[mt][nt][1] * inv0);
            ar1[pos] = packh2(o[mt][nt][2] * inv1, o[mt][nt][3] * inv1);
        }
    }
#undef ATT_LDG
}

// ---------------------------------------------------------------------------
extern "C" void kernel_launch(void* const* d_in, const int* in_sizes, int n_in,
                              void* d_out, int out_size)
{
    const float* x      = (const float*)d_in[0];
    const float* w_qkv  = (const float*)d_in[1];
    const float* b_qkv  = (const float*)d_in[2];
    const float* w_proj = (const float*)d_in[3];
    const float* b_proj = (const float*)d_in[4];
    float* out = (float*)d_out;

    float *qkv_s = nullptr;
    uint32_t *x16_s = nullptr, *att16_s = nullptr;
    uint32_t *wt_s = nullptr, *qt_s = nullptr, *kt_s = nullptr, *vt_s = nullptr;
    cudaGetSymbolAddress((void**)&qkv_s,  g_qkv);
    cudaGetSymbolAddress((void**)&x16_s,  g_x16);
    cudaGetSymbolAddress((void**)&att16_s, g_att16);
    cudaGetSymbolAddress((void**)&wt_s,   g_wt);
    cudaGetSymbolAddress((void**)&qt_s,   g_qt);
    cudaGetSymbolAddress((void**)&kt_s,   g_kt);
    cudaGetSymbolAddress((void**)&vt_s,   g_vt);

    cudaFuncSetAttribute(gemm_mma, cudaFuncAttributeMaxDynamicSharedMemorySize, GEMM_SMEM);
    cudaFuncSetAttribute(attn_mma, cudaFuncAttributeMaxDynamicSharedMemorySize, ATT_SMEM);

    uint32_t* wqkvT = wt_s;
    uint32_t* wprjT = wt_s + (size_t)(3 * DIMC) * (DIMC / 2);

    // 0) weight transposes + x packing (fp16, word-permuted)
    transpose_w<<<dim3((3 * DIMC) / 32, DIMC / 32), dim3(16, 16)>>>(w_qkv, wqkvT, 3 * DIMC);
    transpose_w<<<dim3(DIMC / 32, DIMC / 32), dim3(16, 16)>>>(w_proj, wprjT, DIMC);
    prep_x<<<(MTOK * (DIMC / 2)) / 1024, 256>>>(x, x16_s);

    // 1) QKV GEMM with fused Q/K packing (V written fp32 to g_qkv)
    gemm_mma<<<dim3((3 * DIMC) / 128, MTOK / 128), 256, GEMM_SMEM>>>(
        x16_s, wqkvT, b_qkv, qkv_s, qt_s, kt_s, 3 * DIMC, DIMC, 1);

    // 2) prepass: V transposed fp16 packed
    prep_v<<<dim3(NN / 32, HD / 32, BB * HEADS), dim3(16, 16)>>>(qkv_s, vt_s);

    // 3) flash attention: q-tile 256, 8 warps, mt=2 (grid 384)
    attn_mma<<<BB * HEADS * (NN / 256), 256, ATT_SMEM>>>(qt_s, kt_s, vt_s, att16_s);

    // 4) projection GEMM: [8192,768] @ [768,768] + bias (fp32 out)
    gemm_mma<<<dim3(DIMC / 128, MTOK / 128), 256, GEMM_SMEM>>>(
        att16_s, wprjT, b_proj, out, nullptr, nullptr, DIMC, DIMC, 0);
}

// round 17
// speedup vs baseline: 1.1893x; 1.0312x over previous
#include <cuda_runtime.h>
#include <cuda_fp16.h>
#include <math_constants.h>
#include <cstdint>

#define BB    4
#define NN    2048
#define DIMC  768
#define HEADS 12
#define HD    64
#define MTOK  (BB * NN)   /* 8192 tokens */

// Scratch (allocation-free rule: __device__ globals)
__device__ float    g_qkv[(size_t)MTOK * 3 * DIMC];          // fp32 qkv (V region used)
__device__ uint32_t g_x16[(size_t)MTOK * (DIMC / 2)];        // x packed fp16, NATURAL layout
__device__ uint32_t g_att16[(size_t)MTOK * (DIMC / 2)];      // attn out fp16, NATURAL layout
__device__ uint32_t g_wt[(size_t)(3 * DIMC) * (DIMC / 2) + (size_t)DIMC * (DIMC / 2)]; // W^T fp16x2 NATURAL
__device__ uint32_t g_qt[(size_t)MTOK * (DIMC / 2)];         // Q  [bh][n][32w] fp16x2 p8, prescaled
__device__ uint32_t g_kt[(size_t)MTOK * (DIMC / 2)];         // K  [bh][n][32w] fp16x2 p8
__device__ uint32_t g_vt[(size_t)MTOK * (DIMC / 2)];         // V^T [bh][d][1024w] fp16x2 p8

// ---------------------------------------------------------------------------
// fp16 helpers (sm_80+ PTX only)
// ---------------------------------------------------------------------------
__device__ __forceinline__ uint32_t packh2(float a, float b) {
    __half2 h = __floats2half2_rn(a, b);   // low = a (even k), high = b (odd k)
    return *reinterpret_cast<uint32_t*>(&h);
}

__device__ __forceinline__ void mma_f16(float* d, const uint32_t* a, const uint32_t* b) {
    asm volatile(
        "mma.sync.aligned.m16n8k16.row.col.f32.f16.f16.f32 "
        "{%0,%1,%2,%3}, {%4,%5,%6,%7}, {%8,%9}, {%0,%1,%2,%3};"
        : "+f"(d[0]), "+f"(d[1]), "+f"(d[2]), "+f"(d[3])
        : "r"(a[0]), "r"(a[1]), "r"(a[2]), "r"(a[3]), "r"(b[0]), "r"(b[1]));
}

__device__ __forceinline__ void ldsm_x4(uint32_t* r, uint32_t addr) {
    asm volatile("ldmatrix.sync.aligned.m8n8.x4.shared.b16 {%0,%1,%2,%3}, [%4];"
        : "=r"(r[0]), "=r"(r[1]), "=r"(r[2]), "=r"(r[3]) : "r"(addr));
}

// p8 word permutation (attention buffers only): word w stored at p8(w).
__device__ __forceinline__ int p8(int w)   { return ((w & 3) << 1) + (w >> 2); }

// ===========================================================================
// Weight transpose + fp16 pack:  W[768][Nc] -> WT[Nc][384w]  (NATURAL layout)
// ===========================================================================
__global__ void transpose_w(const float* __restrict__ W, uint32_t* __restrict__ WT, int Nc)
{
    __shared__ float tile[32][33];
    const int kb = blockIdx.y * 32;
    const int nb = blockIdx.x * 32;
    const int tx = threadIdx.x, ty = threadIdx.y;
    const int tid = ty * 16 + tx;
#pragma unroll
    for (int i = 0; i < 4; i++) {
        const int idx = i * 256 + tid;
        const int k = idx >> 5, n = idx & 31;
        tile[k][n] = W[(size_t)(kb + k) * Nc + nb + n];
    }
    __syncthreads();
#pragma unroll
    for (int i = 0; i < 2; i++) {
        const int n = ty + i * 16;
        WT[(size_t)(nb + n) * (DIMC / 2) + (kb >> 1) + tx] =
            packh2(tile[2 * tx][n], tile[2 * tx + 1][n]);
    }
}

// ===========================================================================
// Prepass: x fp32 -> packed fp16 NATURAL layout [8192][384w]
// ===========================================================================
__global__ void prep_x(const float* __restrict__ x, uint32_t* __restrict__ X16)
{
    const size_t base = ((size_t)blockIdx.x * 256 + threadIdx.x) * 4;  // word idx
    const float* src = x + base * 2;
    uint32_t o[4];
#pragma unroll
    for (int j = 0; j < 4; j++)
        o[j] = packh2(src[2 * j], src[2 * j + 1]);
    *(uint4*)&X16[base] = make_uint4(o[0], o[1], o[2], o[3]);
}

// ===========================================================================
// Prepass: V -> V^T [bh][d][1024w] fp16x2, key-pairs p8-permuted (for attention)
// ===========================================================================
__global__ void prep_v(const float* __restrict__ qkv, uint32_t* __restrict__ Vt)
{
    __shared__ float tile[32][33];   // [key][d]
    const int bh = blockIdx.z;
    const int b = bh / HEADS, h = bh % HEADS;
    const int keyb = blockIdx.x * 32, db = blockIdx.y * 32;
    const int tx = threadIdx.x, ty = threadIdx.y;
    const int tid = ty * 16 + tx;
#pragma unroll
    for (int i = 0; i < 4; i++) {
        const int idx = i * 256 + tid;
        const int key = idx >> 5, d = idx & 31;
        tile[key][d] = qkv[(size_t)(b * NN + keyb + key) * (3 * DIMC)
                           + 2 * DIMC + h * HD + db + d];
    }
    __syncthreads();
    const int blk = tx >> 3, wi = tx & 7;
    const int pos = blk * 8 + p8(wi);
#pragma unroll
    for (int i = 0; i < 2; i++) {
        const int d = ty + i * 16;
        Vt[((size_t)bh * HD + db + d) * (NN / 2) + (keyb >> 1) + pos] =
            packh2(tile[2 * tx][d], tile[2 * tx + 1][d]);
    }
}

// ===========================================================================
// GEMM: C[M,N] = A[M,K] @ W[K,N] + bias[N].  NATURAL layouts + ldmatrix.
// 128x128 tile, BK=32, 8 warps (256 threads), warp tile 32x64 (mt=2, nt=8).
// Fragment loads: ldmatrix.m8n8.x4 (12 per thread per k-tile vs 24 LDS.64).
// smem rows stride 36 words (banks 0,4,..,28 -> conflict-free ldmatrix).
// fused!=0: Q/K cols packed (p8) to Qt/Kt; V cols fp32 to C.
// ===========================================================================
#define GSTR 36
#define GBUF 9216                      /* words per buffer: 2 * 128 * 36 */
#define GEMM_SMEM (2 * GBUF * 4)       /* 73728 B */

__global__ __launch_bounds__(256, 2)
void gemm_mma(const uint32_t* __restrict__ A16, const uint32_t* __restrict__ BT,
              const float* __restrict__ bias, float* __restrict__ C,
              uint32_t* __restrict__ Qt, uint32_t* __restrict__ Kt,
              int N, int K, int fused)
{
    extern __shared__ uint32_t dsm[];
    const int tid  = threadIdx.x;
    const int lane = tid & 31, wid = tid >> 5;
    const int g = lane >> 2, t = lane & 3;
    const int bm = blockIdx.y * 128, bn = blockIdx.x * 128;
    const int wm = (wid & 3) * 32, wn = (wid >> 2) * 64;

    const uint32_t smem_b = (uint32_t)__cvta_generic_to_shared(dsm);
    // ldmatrix lane-derived offsets
    const int a_row_l = lane & 15;                       // row within m16
    const int a_chk   = (lane >> 4) * 4;                 // k8-half word offset
    const int b_row_l = (lane & 7) + ((lane >> 4) << 3); // row within n16
    const int b_chk   = ((lane >> 3) & 1) * 4;

    const int ar  = tid >> 1;
    const int ablk = tid & 1;
    const uint32_t* Aq = A16 + (size_t)(bm + ar) * (K / 2) + ablk * 8;
    const uint32_t* Bq = BT  + (size_t)(bn + ar) * (K / 2) + ablk * 8;

    float acc[2][8][4];
#pragma unroll
    for (int mt = 0; mt < 2; mt++)
#pragma unroll
        for (int nt = 0; nt < 8; nt++)
#pragma unroll
            for (int r = 0; r < 4; r++) acc[mt][nt][r] = 0.0f;

    uint4 a_ld[2], b_ld[2];

#define GEMM_LDG(kt) do {                                                    \
    a_ld[0] = *(const uint4*)(Aq + (size_t)(kt) * 16);                       \
    a_ld[1] = *(const uint4*)(Aq + (size_t)(kt) * 16 + 4);                   \
    b_ld[0] = *(const uint4*)(Bq + (size_t)(kt) * 16);                       \
    b_ld[1] = *(const uint4*)(Bq + (size_t)(kt) * 16 + 4);                   \
    } while (0)

#define GEMM_STS(buf) do {                                                   \
    uint32_t* as_ = dsm + (buf) * GBUF;                                      \
    uint32_t* bs_ = as_ + 128 * GSTR;                                        \
    *(uint4*)&as_[ar * GSTR + ablk * 8]     = a_ld[0];                       \
    *(uint4*)&as_[ar * GSTR + ablk * 8 + 4] = a_ld[1];                       \
    *(uint4*)&bs_[ar * GSTR + ablk * 8]     = b_ld[0];                       \
    *(uint4*)&bs_[ar * GSTR + ablk * 8 + 4] = b_ld[1];                       \
    } while (0)

    const int NT = K / 32;
    GEMM_LDG(0);
    GEMM_STS(0);

    for (int kt = 0; kt < NT; kt++) {
        __syncthreads();
        if (kt + 1 < NT) GEMM_LDG(kt + 1);

        const uint32_t as = smem_b + (uint32_t)((kt & 1) * GBUF) * 4u;
        const uint32_t bs = as + 128u * GSTR * 4u;
#pragma unroll
        for (int kb = 0; kb < 2; kb++) {
            uint32_t af[2][4], bf[8][2];
#pragma unroll
            for (int mt = 0; mt < 2; mt++)
                ldsm_x4(af[mt],
                        as + (uint32_t)(((wm + mt * 16 + a_row_l) * GSTR
                                         + kb * 8 + a_chk) * 4));
#pragma unroll
            for (int np = 0; np < 4; np++) {
                uint32_t bq[4];
                ldsm_x4(bq,
                        bs + (uint32_t)(((wn + np * 16 + b_row_l) * GSTR
                                         + kb * 8 + b_chk) * 4));
                bf[2 * np][0]     = bq[0]; bf[2 * np][1]     = bq[1];
                bf[2 * np + 1][0] = bq[2]; bf[2 * np + 1][1] = bq[3];
            }
#pragma unroll
            for (int mt = 0; mt < 2; mt++)
#pragma unroll
                for (int nt = 0; nt < 8; nt++)
                    mma_f16(acc[mt][nt], af[mt], bf[nt]);
        }
        if (kt + 1 < NT) GEMM_STS((kt + 1) & 1);
    }

    // epilogue
    const bool pack_qk = (fused != 0) && (bn + wn < 1536);   // uniform per warp
#pragma unroll
    for (int mt = 0; mt < 2; mt++)
#pragma unroll
        for (int rr = 0; rr < 2; rr++) {
            const int row = bm + wm + mt * 16 + g + rr * 8;
            float* Cr = C + (size_t)row * N;
            const int btok = row >> 11, ntok = row & 2047;
#pragma unroll
            for (int nt = 0; nt < 8; nt++) {
                const int col = bn + wn + nt * 8 + 2 * t;
                float2 bb = *(const float2*)(bias + col);
                const float v0 = acc[mt][nt][rr * 2 + 0] + bb.x;
                const float v1 = acc[mt][nt][rr * 2 + 1] + bb.y;
                if (pack_qk) {
                    const bool isQ = col < 768;
                    const int within = isQ ? col : (col - 768);
                    const int h = within >> 6, d = within & 63;
                    const int w = d >> 1;
                    const int pos = (w & ~7) + p8(w & 7);
                    const uint32_t word = isQ ? packh2(v0 * 0.125f, v1 * 0.125f)
                                              : packh2(v0, v1);
                    uint32_t* dst = isQ ? Qt : Kt;
                    dst[((size_t)(btok * HEADS + h) * NN + ntok) * (HD / 2) + pos] = word;
                } else {
                    float2 o; o.x = v0; o.y = v1;
                    *(float2*)(Cr + col) = o;
                }
            }
        }
#undef GEMM_LDG
#undef GEMM_STS
}

// ===========================================================================
// Flash attention (unchanged from R16 except NATURAL att16 epilogue).
// 8 warps, q-tile 256, warp = 32 q-rows (mt=2). Q in regs, P from regs.
// K/V double-buffered (p8 layout), one sync per tile.
// smem words: 2 bufs x (Ks 2560 | Vs 2560) = 10240 (40960 B)
// ===========================================================================
#define AST 40
#define ATT_SMEM (10240 * 4)

__global__ __launch_bounds__(256, 1)
void attn_mma(const uint32_t* __restrict__ Qt, const uint32_t* __restrict__ Kt,
              const uint32_t* __restrict__ Vt, uint32_t* __restrict__ att16)
{
    extern __shared__ uint32_t dsm[];
    const int tid = threadIdx.x, lane = tid & 31, w = tid >> 5;   // 8 warps
    const int g = lane >> 2, t = lane & 3;
    const int qt = blockIdx.x & 7;                 // 8 q-tiles of 256
    const int h  = (blockIdx.x >> 3) % HEADS;
    const int b  = blockIdx.x / (8 * HEADS);
    const int bh = b * HEADS + h;
    const int q0 = qt * 256;
    const int r0 = 32 * w + g;          // warp covers rows [32w, 32w+32)

    // ---- Q fragments (two m-tiles) straight into registers ----
    uint32_t qa[2][4][4];
#pragma unroll
    for (int mt = 0; mt < 2; mt++) {
        const uint32_t* Qr0 = Qt + ((size_t)bh * NN + q0 + r0 + 16 * mt) * (HD / 2);
        const uint32_t* Qr8 = Qr0 + 8 * (HD / 2);
#pragma unroll
        for (int kb = 0; kb < 4; kb++) {
            uint2 lo = *(const uint2*)&Qr0[kb * 8 + 2 * t];
            uint2 hi = *(const uint2*)&Qr8[kb * 8 + 2 * t];
            qa[mt][kb][0] = lo.x; qa[mt][kb][1] = hi.x;
            qa[mt][kb][2] = lo.y; qa[mt][kb][3] = hi.y;
        }
    }

    float o[2][8][4];
#pragma unroll
    for (int mt = 0; mt < 2; mt++)
#pragma unroll
        for (int nt = 0; nt < 8; nt++)
#pragma unroll
            for (int r = 0; r < 4; r++) o[mt][nt][r] = 0.0f;
    float m_[2][2], l_[2][2];
#pragma unroll
    for (int mt = 0; mt < 2; mt++) {
        m_[mt][0] = -CUDART_INF_F; m_[mt][1] = -CUDART_INF_F;
        l_[mt][0] = 0.0f;          l_[mt][1] = 0.0f;
    }

    const uint32_t* Kbase = Kt + (size_t)bh * NN * (HD / 2);
    const uint32_t* Vbase = Vt + (size_t)bh * HD * (NN / 2);

    const int ld_row = tid >> 3, ld_c = (tid & 7) * 4;   // 32 rows/chunk, 2 chunks

    uint4 kf[2], vf[2];
#define ATT_LDG(kt) do {                                                      \
    _Pragma("unroll")                                                         \
    for (int j = 0; j < 2; j++) {                                             \
        kf[j] = *(const uint4*)&Kbase[((size_t)(kt) * 64 + ld_row + 32 * j) * (HD / 2) + ld_c]; \
        vf[j] = *(const uint4*)&Vbase[(size_t)(ld_row + 32 * j) * (NN / 2) + (kt) * 32 + ld_c]; \
    } } while (0)

    ATT_LDG(0);

    for (int kt = 0; kt < NN / 64; kt++) {
        const int base = (kt & 1) * 5120;           // [Ks 2560 | Vs 2560]
#pragma unroll
        for (int j = 0; j < 2; j++) {
            *(uint4*)&dsm[base + (ld_row + 32 * j) * AST + ld_c]        = kf[j];
            *(uint4*)&dsm[base + 2560 + (ld_row + 32 * j) * AST + ld_c] = vf[j];
        }
        __syncthreads();
        if (kt + 1 < NN / 64) ATT_LDG(kt + 1);   // overlaps compute below

        // ---- S = Q @ K^T : K frags shared across both m-tiles ----
        float s[2][8][4];
#pragma unroll
        for (int mt = 0; mt < 2; mt++)
#pragma unroll
            for (int nt = 0; nt < 8; nt++)
#pragma unroll
                for (int r = 0; r < 4; r++) s[mt][nt][r] = 0.0f;

#pragma unroll
        for (int kb = 0; kb < 4; kb++) {
#pragma unroll
            for (int nt = 0; nt < 8; nt++) {
                uint2 bb = *(const uint2*)&dsm[base + (nt * 8 + g) * AST + kb * 8 + 2 * t];
                uint32_t bf2[2] = {bb.x, bb.y};
                mma_f16(s[0][nt], qa[0][kb], bf2);
                mma_f16(s[1][nt], qa[1][kb], bf2);
            }
        }

        // ---- online softmax per m-tile (rows g and g+8; quad-local) ----
#pragma unroll
        for (int mt = 0; mt < 2; mt++) {
            float mx0 = -CUDART_INF_F, mx1 = -CUDART_INF_F;
#pragma unroll
            for (int nt = 0; nt < 8; nt++) {
                mx0 = fmaxf(mx0, fmaxf(s[mt][nt][0], s[mt][nt][1]));
                mx1 = fmaxf(mx1, fmaxf(s[mt][nt][2], s[mt][nt][3]));
            }
            mx0 = fmaxf(mx0, __shfl_xor_sync(0xffffffffu, mx0, 1));
            mx0 = fmaxf(mx0, __shfl_xor_sync(0xffffffffu, mx0, 2));
            mx1 = fmaxf(mx1, __shfl_xor_sync(0xffffffffu, mx1, 1));
            mx1 = fmaxf(mx1, __shfl_xor_sync(0xffffffffu, mx1, 2));
            const float nm0 = fmaxf(m_[mt][0], mx0), nm1 = fmaxf(m_[mt][1], mx1);
            const float cr0 = __expf(m_[mt][0] - nm0), cr1 = __expf(m_[mt][1] - nm1);
            float rs0 = 0.0f, rs1 = 0.0f;
#pragma unroll
            for (int nt = 0; nt < 8; nt++) {
                s[mt][nt][0] = __expf(s[mt][nt][0] - nm0);
                s[mt][nt][1] = __expf(s[mt][nt][1] - nm0);
                s[mt][nt][2] = __expf(s[mt][nt][2] - nm1);
                s[mt][nt][3] = __expf(s[mt][nt][3] - nm1);
                rs0 += s[mt][nt][0] + s[mt][nt][1];
                rs1 += s[mt][nt][2] + s[mt][nt][3];
            }
            rs0 += __shfl_xor_sync(0xffffffffu, rs0, 1);
            rs0 += __shfl_xor_sync(0xffffffffu, rs0, 2);
            rs1 += __shfl_xor_sync(0xffffffffu, rs1, 1);
            rs1 += __shfl_xor_sync(0xffffffffu, rs1, 2);
            l_[mt][0] = l_[mt][0] * cr0 + rs0;  m_[mt][0] = nm0;
            l_[mt][1] = l_[mt][1] * cr1 + rs1;  m_[mt][1] = nm1;
#pragma unroll
            for (int nt = 0; nt < 8; nt++) {
                o[mt][nt][0] *= cr0; o[mt][nt][1] *= cr0;
                o[mt][nt][2] *= cr1; o[mt][nt][3] *= cr1;
            }
        }

        // ---- O += P @ V : P from registers; V frags shared across m-tiles ----
#pragma unroll
        for (int kb = 0; kb < 4; kb++) {
            uint32_t a[2][4];
#pragma unroll
            for (int mt = 0; mt < 2; mt++) {
                a[mt][0] = packh2(s[mt][2 * kb][0],     s[mt][2 * kb][1]);
                a[mt][1] = packh2(s[mt][2 * kb][2],     s[mt][2 * kb][3]);
                a[mt][2] = packh2(s[mt][2 * kb + 1][0], s[mt][2 * kb + 1][1]);
                a[mt][3] = packh2(s[mt][2 * kb + 1][2], s[mt][2 * kb + 1][3]);
            }
#pragma unroll
            for (int nt = 0; nt < 8; nt++) {
                uint2 bb = *(const uint2*)&dsm[base + 2560 + (nt * 8 + g) * AST + kb * 8 + 2 * t];
                uint32_t bf2[2] = {bb.x, bb.y};
                mma_f16(o[0][nt], a[0], bf2);
                mma_f16(o[1][nt], a[1], bf2);
            }
        }
    }

    // ---- epilogue: normalize, write packed fp16 in NATURAL A-layout ----
#pragma unroll
    for (int mt = 0; mt < 2; mt++) {
        const float inv0 = 1.0f / l_[mt][0], inv1 = 1.0f / l_[mt][1];
        const int grow = b * NN + q0 + r0 + 16 * mt;
        uint32_t* ar0 = att16 + (size_t)grow * (DIMC / 2);
        uint32_t* ar1 = att16 + (size_t)(grow + 8) * (DIMC / 2);
#pragma unroll
        for (int nt = 0; nt < 8; nt++) {
            const int wd = h * 32 + 4 * nt + t;            // natural word index
            ar0[wd] = packh2(o[mt][nt][0] * inv0, o[mt][nt][1] * inv0);
            ar1[wd] = packh2(o[mt][nt][2] * inv1, o[mt][nt][3] * inv1);
        }
    }
#undef ATT_LDG
}

// ---------------------------------------------------------------------------
extern "C" void kernel_launch(void* const* d_in, const int* in_sizes, int n_in,
                              void* d_out, int out_size)
{
    const float* x      = (const float*)d_in[0];
    const float* w_qkv  = (const float*)d_in[1];
    const float* b_qkv  = (const float*)d_in[2];
    const float* w_proj = (const float*)d_in[3];
    const float* b_proj = (const float*)d_in[4];
    float* out = (float*)d_out;

    float *qkv_s = nullptr;
    uint32_t *x16_s = nullptr, *att16_s = nullptr;
    uint32_t *wt_s = nullptr, *qt_s = nullptr, *kt_s = nullptr, *vt_s = nullptr;
    cudaGetSymbolAddress((void**)&qkv_s,  g_qkv);
    cudaGetSymbolAddress((void**)&x16_s,  g_x16);
    cudaGetSymbolAddress((void**)&att16_s, g_att16);
    cudaGetSymbolAddress((void**)&wt_s,   g_wt);
    cudaGetSymbolAddress((void**)&qt_s,   g_qt);
    cudaGetSymbolAddress((void**)&kt_s,   g_kt);
    cudaGetSymbolAddress((void**)&vt_s,   g_vt);

    cudaFuncSetAttribute(gemm_mma, cudaFuncAttributeMaxDynamicSharedMemorySize, GEMM_SMEM);
    cudaFuncSetAttribute(attn_mma, cudaFuncAttributeMaxDynamicSharedMemorySize, ATT_SMEM);

    uint32_t* wqkvT = wt_s;
    uint32_t* wprjT = wt_s + (size_t)(3 * DIMC) * (DIMC / 2);

    // 0) weight transposes + x packing (fp16, NATURAL layout)
    transpose_w<<<dim3((3 * DIMC) / 32, DIMC / 32), dim3(16, 16)>>>(w_qkv, wqkvT, 3 * DIMC);
    transpose_w<<<dim3(DIMC / 32, DIMC / 32), dim3(16, 16)>>>(w_proj, wprjT, DIMC);
    prep_x<<<(MTOK * (DIMC / 2)) / 1024, 256>>>(x, x16_s);

    // 1) QKV GEMM with fused Q/K packing (V written fp32 to g_qkv)
    gemm_mma<<<dim3((3 * DIMC) / 128, MTOK / 128), 256, GEMM_SMEM>>>(
        x16_s, wqkvT, b_qkv, qkv_s, qt_s, kt_s, 3 * DIMC, DIMC, 1);

    // 2) prepass: V transposed fp16 packed (p8)
    prep_v<<<dim3(NN / 32, HD / 32, BB * HEADS), dim3(16, 16)>>>(qkv_s, vt_s);

    // 3) flash attention: q-tile 256, 8 warps, mt=2 (grid 384)
    attn_mma<<<BB * HEADS * (NN / 256), 256, ATT_SMEM>>>(qt_s, kt_s, vt_s, att16_s);

    // 4) projection GEMM: [8192,768] @ [768,768] + bias (fp32 out)
    gemm_mma<<<dim3(DIMC / 128, MTOK / 128), 256, GEMM_SMEM>>>(
        att16_s, wprjT, b_proj, out, nullptr, nullptr, DIMC, DIMC, 0);
}